// round 3
// baseline (speedup 1.0000x reference)
#include <cuda_runtime.h>
#include <math.h>
#include <float.h>

#define BB 8
#define CC 128
#define SS 32768
#define NTOK (BB*SS)            // 262144
#define EE 512
#define MARGIN 1.0e-4f

#define OUT_Q_OFF 1LL
#define PERP_OFF  (1LL + (long long)BB*CC*SS)   // 33554433
#define ENC_OFF   (PERP_OFF + 1LL)              // 33554434

// ---------------- scratch (device globals) ----------------------------------
__device__ float        g_sww[EE];       // fl(||w_e||^2), correctly rounded
__device__ unsigned int g_counts[EE];
__device__ double       g_sse;
__device__ int          g_idx[NTOK];
__device__ int          g_amb[NTOK];
__device__ int          g_amb_count;

// ---------------- prep: sww (double -> fp32) + zero accumulators ------------
__global__ void prep_kernel(const float* __restrict__ w) {
    int gw   = (blockIdx.x * blockDim.x + threadIdx.x) >> 5;
    int lane = threadIdx.x & 31;
    if (gw < EE) {
        const float* wr = w + gw * CC;
        double s = 0.0;
#pragma unroll
        for (int j = 0; j < 4; j++) {
            float v = wr[lane * 4 + j];
            s += (double)v * (double)v;
        }
#pragma unroll
        for (int off = 16; off; off >>= 1)
            s += __shfl_down_sync(0xFFFFFFFFu, s, off);
        if (lane == 0) g_sww[gw] = (float)s;
    }
    if (blockIdx.x == 0 && threadIdx.x < EE) g_counts[threadIdx.x] = 0u;
    if (blockIdx.x == 0 && threadIdx.x == 0) { g_sse = 0.0; g_amb_count = 0; }
}

// ---------------- pass 1: fp32 GEMM + top-2 tracking ------------------------
#define TM 128
#define TCHUNK 64
#define WS_STRIDE 65
#define SMEM_FLOATS (CC*TM + CC*WS_STRIDE)      // 24704 floats

extern __shared__ float sdyn[];

__global__ __launch_bounds__(256) void pass1_kernel(const float* __restrict__ x,
                                                    const float* __restrict__ w) {
    float* xs = sdyn;                 // [128][128]
    float* ws = sdyn + CC * TM;       // [128][65]

    const int b  = blockIdx.x >> 8;
    const int s0 = (blockIdx.x & 255) << 7;
    const int tid = threadIdx.x;

    const float* xb = x + ((long long)b * CC) * SS + s0;
    for (int i = tid; i < CC * TM; i += 256) {
        int k = i >> 7, t = i & 127;
        xs[i] = xb[(long long)k * SS + t];
    }

    const int ty = tid >> 4;
    const int tx = tid & 15;
    const int t0 = ty * 8;
    const int c0 = tx * 4;

    float m1[8], m2[8];
    int   i1[8];
#pragma unroll
    for (int i = 0; i < 8; i++) { m1[i] = FLT_MAX; m2[i] = FLT_MAX; i1[i] = 0x7FFFFFFF; }

    for (int cc = 0; cc < EE; cc += TCHUNK) {
        __syncthreads();
        for (int i = tid; i < TCHUNK * CC; i += 256) {
            int code = i >> 7, k = i & 127;
            ws[k * WS_STRIDE + code] = w[(cc + code) * CC + k];
        }
        __syncthreads();

        float acc[8][4];
#pragma unroll
        for (int i = 0; i < 8; i++)
#pragma unroll
            for (int j = 0; j < 4; j++) acc[i][j] = 0.f;

#pragma unroll 2
        for (int k = 0; k < CC; k++) {
            float4 xa = *(const float4*)&xs[k * TM + t0];
            float4 xv = *(const float4*)&xs[k * TM + t0 + 4];
            float xr[8] = {xa.x, xa.y, xa.z, xa.w, xv.x, xv.y, xv.z, xv.w};
            float w0 = ws[k * WS_STRIDE + c0 + 0];
            float w1 = ws[k * WS_STRIDE + c0 + 1];
            float w2 = ws[k * WS_STRIDE + c0 + 2];
            float w3 = ws[k * WS_STRIDE + c0 + 3];
#pragma unroll
            for (int i = 0; i < 8; i++) {
                acc[i][0] = fmaf(xr[i], w0, acc[i][0]);
                acc[i][1] = fmaf(xr[i], w1, acc[i][1]);
                acc[i][2] = fmaf(xr[i], w2, acc[i][2]);
                acc[i][3] = fmaf(xr[i], w3, acc[i][3]);
            }
        }

        // score = sww - 2*dot   (sxx is per-token constant; ordering proxy)
#pragma unroll
        for (int j = 0; j < 4; j++) {
            int id = cc + c0 + j;
            float sw = g_sww[id];
#pragma unroll
            for (int i = 0; i < 8; i++) {
                float sc = fmaf(-2.f, acc[i][j], sw);
                if (sc < m1[i]) { m2[i] = m1[i]; m1[i] = sc; i1[i] = id; }
                else            { m2[i] = fminf(m2[i], sc); }
            }
        }
    }

    // cross-thread reduce (16 threads share each token)
    __syncthreads();
    float* rv1 = ws;                        // [128][16]
    int*   ri1 = (int*)(ws + TM * 16);      // [128][16]
    float* rv2 = ws + TM * 32;              // [128][16]
#pragma unroll
    for (int i = 0; i < 8; i++) {
        int t = t0 + i;
        rv1[t * 16 + tx] = m1[i];
        ri1[t * 16 + tx] = i1[i];
        rv2[t * 16 + tx] = m2[i];
    }
    __syncthreads();

    if (tid < TM) {
        float b1 = FLT_MAX, b2 = FLT_MAX;
        int   bi = 0x7FFFFFFF;
#pragma unroll
        for (int j = 0; j < 16; j++) {
            float v1 = rv1[tid * 16 + j];
            int   ii = ri1[tid * 16 + j];
            float v2 = rv2[tid * 16 + j];
            if (v1 < b1 || (v1 == b1 && ii < bi)) { b2 = fminf(b2, b1); b1 = v1; bi = ii; }
            else b2 = fminf(b2, v1);
            b2 = fminf(b2, v2);
        }
        int token = b * SS + s0 + tid;
        g_idx[token] = bi;
        if (b2 - b1 < MARGIN) {
            int p = atomicAdd(&g_amb_count, 1);
            g_amb[p] = token;
        }
    }
}

// ---------------- pass 2: fp32-exact reference emulation --------------------
// d_e = fl( fl(sxx + sww_e) - 2*m_e ),  m_e correctly rounded via double acc.
__global__ __launch_bounds__(256) void pass2_kernel(const float* __restrict__ x,
                                                    const float* __restrict__ w) {
    __shared__ float xs_s[8][128];
    const int wid = threadIdx.x >> 5, lane = threadIdx.x & 31;
    const int gw = blockIdx.x * 8 + wid;
    const int nW = gridDim.x * 8;
    const int cnt = g_amb_count;

    for (int it = gw; it < cnt; it += nW) {
        int token = g_amb[it];
        int b = token >> 15, s = token & 32767;
        const float* xb = x + ((long long)b * CC) * SS + s;

        double sx = 0.0;
#pragma unroll
        for (int j = 0; j < 4; j++) {
            float v = xb[(long long)(lane * 4 + j) * SS];
            xs_s[wid][lane * 4 + j] = v;
            sx += (double)v * (double)v;
        }
#pragma unroll
        for (int off = 16; off; off >>= 1)
            sx += __shfl_down_sync(0xFFFFFFFFu, sx, off);
        float sxx = (float)__shfl_sync(0xFFFFFFFFu, sx, 0);
        __syncwarp();

        float bd = FLT_MAX; int bi = 0x7FFFFFFF;
        for (int e = lane; e < EE; e += 32) {
            const float* wr = w + e * CC;
            double a = 0.0;
#pragma unroll 4
            for (int k = 0; k < CC; k++)
                a += (double)xs_s[wid][k] * (double)wr[k];
            float m = (float)a;
            float d = __fsub_rn(__fadd_rn(sxx, g_sww[e]), 2.0f * m);
            if (d < bd) { bd = d; bi = e; }          // ascending e -> first min
        }
#pragma unroll
        for (int off = 16; off; off >>= 1) {
            float od = __shfl_down_sync(0xFFFFFFFFu, bd, off);
            int   oi = __shfl_down_sync(0xFFFFFFFFu, bi, off);
            if (od < bd || (od == bd && oi < bi)) { bd = od; bi = oi; }
        }
        if (lane == 0) g_idx[token] = bi;
        __syncwarp();
    }
}

// ---------------- histogram (post pass-2) -----------------------------------
__global__ __launch_bounds__(512) void hist_kernel() {
    __shared__ unsigned int sh[EE];
    for (int i = threadIdx.x; i < EE; i += 512) sh[i] = 0u;
    __syncthreads();
    for (int n = blockIdx.x * 512 + threadIdx.x; n < NTOK; n += gridDim.x * 512)
        atomicAdd(&sh[g_idx[n]], 1u);
    __syncthreads();
    for (int i = threadIdx.x; i < EE; i += 512) {
        unsigned int h = sh[i];
        if (h) atomicAdd(&g_counts[i], h);
    }
}

// ---------------- out_q (gather + transpose) + fused MSE --------------------
__global__ __launch_bounds__(256) void outq_kernel(const float* __restrict__ x,
                                                   const float* __restrict__ w,
                                                   float* __restrict__ out) {
    __shared__ float qs[64 * 129];
    __shared__ int   idxs[64];
    __shared__ float wsum[8];

    const int b  = blockIdx.x >> 9;
    const int s0 = (blockIdx.x & 511) << 6;
    const int tid = threadIdx.x;

    if (tid < 64) idxs[tid] = g_idx[b * SS + s0 + tid];
    __syncthreads();

    for (int i = tid; i < 64 * CC; i += 256) {
        int t = i >> 7, k = i & 127;
        qs[t * 129 + k] = w[idxs[t] * CC + k];
    }
    __syncthreads();

    const float* xb = x + ((long long)b * CC) * SS + s0;
    float* ob = out + OUT_Q_OFF + ((long long)b * CC) * SS + s0;
    float lsum = 0.f;
    for (int i = tid; i < CC * 64; i += 256) {
        int c = i >> 6, t = i & 63;
        float q = qs[t * 129 + c];
        long long off = (long long)c * SS + t;
        float xv = xb[off];
        ob[off] = q;
        float d = q - xv;
        lsum = fmaf(d, d, lsum);
    }
#pragma unroll
    for (int o = 16; o > 0; o >>= 1)
        lsum += __shfl_down_sync(0xFFFFFFFFu, lsum, o);
    if ((tid & 31) == 0) wsum[tid >> 5] = lsum;
    __syncthreads();
    if (tid == 0) {
        double ssum = 0.0;
#pragma unroll
        for (int i = 0; i < 8; i++) ssum += (double)wsum[i];
        atomicAdd(&g_sse, ssum);
    }
}

// ---------------- one-hot scatter --------------------------------------------
__global__ void scatter_kernel(float* __restrict__ out) {
    int n = blockIdx.x * 256 + threadIdx.x;
    out[ENC_OFF + (long long)n * EE + g_idx[n]] = 1.0f;
}

// ---------------- finalize: loss + perplexity --------------------------------
__global__ void finalize_kernel(float* __restrict__ out) {
    __shared__ double ssum[EE];
    int e = threadIdx.x;
    double p = (double)g_counts[e] / (double)NTOK;
    ssum[e] = p * log(p + 1e-10);
    __syncthreads();
    for (int s = 256; s > 0; s >>= 1) {
        if (e < s) ssum[e] += ssum[e + s];
        __syncthreads();
    }
    if (e == 0) {
        out[PERP_OFF] = (float)exp(-ssum[0]);
        out[0] = (float)(1.25 * g_sse / (double)((long long)NTOK * CC));
    }
}

// ---------------- launch ------------------------------------------------------
extern "C" void kernel_launch(void* const* d_in, const int* in_sizes, int n_in,
                              void* d_out, int out_size) {
    const float* x = (const float*)d_in[0];   // (8,128,32,32,32) fp32
    const float* w = (const float*)d_in[1];   // (512,128) fp32
    float* out = (float*)d_out;

    cudaFuncSetAttribute(pass1_kernel, cudaFuncAttributeMaxDynamicSharedMemorySize,
                         SMEM_FLOATS * (int)sizeof(float));

    prep_kernel<<<16, 1024>>>(w);
    cudaMemsetAsync(out + ENC_OFF, 0, (size_t)NTOK * EE * sizeof(float));
    pass1_kernel<<<NTOK / TM, 256, SMEM_FLOATS * sizeof(float)>>>(x, w);
    pass2_kernel<<<256, 256>>>(x, w);
    hist_kernel<<<512, 512>>>();
    outq_kernel<<<NTOK / 64, 256>>>(x, w, out);
    scatter_kernel<<<NTOK / 256, 256>>>(out);
    finalize_kernel<<<1, EE>>>(out);
}